// round 15
// baseline (speedup 1.0000x reference)
#include <cuda_runtime.h>

// y[h] = a0*x[h] + a1*(x[h-1]+x[h+1]) + a2*(x[h-2]+x[h+2]) + a3*(x[h-3]+x[h+3])
// reflect indexing along H. x: (N, C, 256, 256) fp32, alpha: (C, 4) fp32.

#define HH 256
#define WW 256
#define W4 (WW / 4)           // 64 float4 per row
#define SEG 64                // output rows per work unit
#define SEGS (HH / SEG)       // 4
#define UNITS_PER_BLOCK 4     // 4 * 64 lanes = 256 threads

__device__ __forceinline__ int refl(int i) {
    i = (i < 0) ? -i : i;
    return (i < HH) ? i : (2 * HH - 2 - i);
}

__global__ __launch_bounds__(256, 2)
void hartley_conv_kernel(const float4* __restrict__ x,
                         const float*  __restrict__ alpha,
                         float4* __restrict__ y,
                         int nunits, int C)
{
    const int unit = blockIdx.x * UNITS_PER_BLOCK + (threadIdx.x >> 6);
    const int lane = threadIdx.x & 63;
    if (unit >= nunits) return;

    const int seg   = unit & (SEGS - 1);
    const int plane = unit >> 2;          // SEGS == 4
    const int h0    = seg * SEG;

    const int c = plane % C;
    const float a0 = alpha[c * 4 + 0];
    const float a1 = alpha[c * 4 + 1];
    const float a2 = alpha[c * 4 + 2];
    const float a3 = alpha[c * 4 + 3];

    const float4* __restrict__ xp = x + (size_t)plane * (HH * W4) + lane;
    float4*       __restrict__ yp = y + ((size_t)plane * HH + h0) * W4 + lane;

    // Invariant at top of iter i (global row h = h0+i):
    //   w0..w6 = rows h-3 .. h+3 (reflected), n0..n7 = rows h+4 .. h+11
    float4 w0, w1, w2, w3, w4, w5, w6;
    float4 n0, n1, n2, n3, n4, n5, n6, n7;
    w0 = __ldcs(xp + refl(h0 - 3) * W4);
    w1 = __ldcs(xp + refl(h0 - 2) * W4);
    w2 = __ldcs(xp + refl(h0 - 1) * W4);
    w3 = __ldcs(xp + (h0 + 0) * W4);
    w4 = __ldcs(xp + (h0 + 1) * W4);
    w5 = __ldcs(xp + (h0 + 2) * W4);
    w6 = __ldcs(xp + (h0 + 3) * W4);
    n0 = __ldcs(xp + (h0 + 4) * W4);
    n1 = __ldcs(xp + (h0 + 5) * W4);
    n2 = __ldcs(xp + (h0 + 6) * W4);
    n3 = __ldcs(xp + (h0 + 7) * W4);
    n4 = __ldcs(xp + (h0 + 8) * W4);
    n5 = __ldcs(xp + (h0 + 9) * W4);
    n6 = __ldcs(xp + (h0 + 10) * W4);
    n7 = __ldcs(xp + (h0 + 11) * W4);

#define TAP(o, p0, p1, p2, p3_, p4, p5, p6)                                                \
    o.x = fmaf(a3, p0.x + p6.x, fmaf(a2, p1.x + p5.x, fmaf(a1, p2.x + p4.x, a0 * p3_.x))); \
    o.y = fmaf(a3, p0.y + p6.y, fmaf(a2, p1.y + p5.y, fmaf(a1, p2.y + p4.y, a0 * p3_.y))); \
    o.z = fmaf(a3, p0.z + p6.z, fmaf(a2, p1.z + p5.z, fmaf(a1, p2.z + p4.z, a0 * p3_.z))); \
    o.w = fmaf(a3, p0.w + p6.w, fmaf(a2, p1.w + p5.w, fmaf(a1, p2.w + p4.w, a0 * p3_.w)))

    #pragma unroll 1
    for (int i = 0; i < SEG; i += 8) {
        const int g = h0 + i;

        // First half-batch of next-iteration rows (g+12..g+15), unconditional.
        float4 m0 = __ldcs(xp + refl(g + 12) * W4);
        float4 m1 = __ldcs(xp + refl(g + 13) * W4);
        float4 m2 = __ldcs(xp + refl(g + 14) * W4);
        float4 m3 = __ldcs(xp + refl(g + 15) * W4);

        // Rows g..g+3 (consume w0..w3; afterwards w0..w3 are dead).
        float4 o;
        TAP(o, w0, w1, w2, w3, w4, w5, w6); __stcs(yp + (i + 0) * W4, o);
        TAP(o, w1, w2, w3, w4, w5, w6, n0); __stcs(yp + (i + 1) * W4, o);
        TAP(o, w2, w3, w4, w5, w6, n0, n1); __stcs(yp + (i + 2) * W4, o);
        TAP(o, w3, w4, w5, w6, n0, n1, n2); __stcs(yp + (i + 3) * W4, o);

        // Second half-batch (g+16..g+19) — after w0..w3 freed (no spill).
        float4 m4 = __ldcs(xp + refl(g + 16) * W4);
        float4 m5 = __ldcs(xp + refl(g + 17) * W4);
        float4 m6 = __ldcs(xp + refl(g + 18) * W4);
        float4 m7 = __ldcs(xp + refl(g + 19) * W4);

        // Rows g+4..g+7.
        TAP(o, w4, w5, w6, n0, n1, n2, n3); __stcs(yp + (i + 4) * W4, o);
        TAP(o, w5, w6, n0, n1, n2, n3, n4); __stcs(yp + (i + 5) * W4, o);
        TAP(o, w6, n0, n1, n2, n3, n4, n5); __stcs(yp + (i + 6) * W4, o);
        TAP(o, n0, n1, n2, n3, n4, n5, n6); __stcs(yp + (i + 7) * W4, o);

        // Shift window by 8 rows.
        w0 = n1; w1 = n2; w2 = n3; w3 = n4; w4 = n5; w5 = n6; w6 = n7;
        n0 = m0; n1 = m1; n2 = m2; n3 = m3; n4 = m4; n5 = m5; n6 = m6; n7 = m7;
    }
#undef TAP
}

extern "C" void kernel_launch(void* const* d_in, const int* in_sizes, int n_in,
                              void* d_out, int out_size)
{
    const float4* x     = (const float4*)d_in[0];
    const float*  alpha = (const float*)d_in[1];
    float4*       y     = (float4*)d_out;

    const int C      = in_sizes[1] / 4;          // alpha is (C, 4)
    const int planes = in_sizes[0] / (HH * WW);  // N * C
    const int nunits = planes * SEGS;

    const int grid = (nunits + UNITS_PER_BLOCK - 1) / UNITS_PER_BLOCK;
    hartley_conv_kernel<<<grid, 256>>>(x, alpha, y, nunits, C);
}

// round 16
// speedup vs baseline: 1.0348x; 1.0348x over previous
#include <cuda_runtime.h>

// y[h] = a0*x[h] + a1*(x[h-1]+x[h+1]) + a2*(x[h-2]+x[h+2]) + a3*(x[h-3]+x[h+3])
// reflect indexing along H. x: (N, C, 256, 256) fp32, alpha: (C, 4) fp32.

#define HH 256
#define WW 256
#define W4 (WW / 4)           // 64 float4 per row
#define SEG 128               // output rows per work unit (2 units per plane)
#define SEGS (HH / SEG)       // 2

__device__ __forceinline__ int refl(int i) {
    i = (i < 0) ? -i : i;
    return (i < HH) ? i : (2 * HH - 2 - i);
}

// One 64-thread block per (plane, half) unit. 8 blocks/SM -> 1024-unit grid
// fits in a single wave (capacity 1184), per-SM load 6.92 -> 98.8% balance.
__global__ __launch_bounds__(64, 8)
void hartley_conv_kernel(const float4* __restrict__ x,
                         const float*  __restrict__ alpha,
                         float4* __restrict__ y,
                         int nunits, int C)
{
    const int unit = blockIdx.x;
    const int lane = threadIdx.x;   // 0..63
    if (unit >= nunits) return;

    const int seg   = unit & (SEGS - 1);
    const int plane = unit >> 1;          // SEGS == 2
    const int h0    = seg * SEG;

    const int c = plane % C;
    const float a0 = alpha[c * 4 + 0];
    const float a1 = alpha[c * 4 + 1];
    const float a2 = alpha[c * 4 + 2];
    const float a3 = alpha[c * 4 + 3];

    const float4* __restrict__ xp = x + (size_t)plane * (HH * W4) + lane;
    float4*       __restrict__ yp = y + ((size_t)plane * HH + h0) * W4 + lane;

    // Invariant at top of iter i (global row h = h0+i):
    //   w0..w6 = rows h-3 .. h+3 (reflected), n0..n7 = rows h+4 .. h+11
    float4 w0, w1, w2, w3, w4, w5, w6;
    float4 n0, n1, n2, n3, n4, n5, n6, n7;
    w0 = __ldcs(xp + refl(h0 - 3) * W4);
    w1 = __ldcs(xp + refl(h0 - 2) * W4);
    w2 = __ldcs(xp + refl(h0 - 1) * W4);
    w3 = __ldcs(xp + (h0 + 0) * W4);
    w4 = __ldcs(xp + (h0 + 1) * W4);
    w5 = __ldcs(xp + (h0 + 2) * W4);
    w6 = __ldcs(xp + (h0 + 3) * W4);
    n0 = __ldcs(xp + (h0 + 4) * W4);
    n1 = __ldcs(xp + (h0 + 5) * W4);
    n2 = __ldcs(xp + (h0 + 6) * W4);
    n3 = __ldcs(xp + (h0 + 7) * W4);
    n4 = __ldcs(xp + (h0 + 8) * W4);
    n5 = __ldcs(xp + (h0 + 9) * W4);
    n6 = __ldcs(xp + (h0 + 10) * W4);
    n7 = __ldcs(xp + (h0 + 11) * W4);

#define TAP(o, p0, p1, p2, p3_, p4, p5, p6)                                                \
    o.x = fmaf(a3, p0.x + p6.x, fmaf(a2, p1.x + p5.x, fmaf(a1, p2.x + p4.x, a0 * p3_.x))); \
    o.y = fmaf(a3, p0.y + p6.y, fmaf(a2, p1.y + p5.y, fmaf(a1, p2.y + p4.y, a0 * p3_.y))); \
    o.z = fmaf(a3, p0.z + p6.z, fmaf(a2, p1.z + p5.z, fmaf(a1, p2.z + p4.z, a0 * p3_.z))); \
    o.w = fmaf(a3, p0.w + p6.w, fmaf(a2, p1.w + p5.w, fmaf(a1, p2.w + p4.w, a0 * p3_.w)))

    #pragma unroll 1
    for (int i = 0; i < SEG; i += 8) {
        const int g = h0 + i;

        // First half-batch of next-iteration rows (g+12..g+15), unconditional.
        float4 m0 = __ldcs(xp + refl(g + 12) * W4);
        float4 m1 = __ldcs(xp + refl(g + 13) * W4);
        float4 m2 = __ldcs(xp + refl(g + 14) * W4);
        float4 m3 = __ldcs(xp + refl(g + 15) * W4);

        // Rows g..g+3 (consume w0..w3; afterwards w0..w3 are dead).
        float4 o;
        TAP(o, w0, w1, w2, w3, w4, w5, w6); __stcs(yp + (i + 0) * W4, o);
        TAP(o, w1, w2, w3, w4, w5, w6, n0); __stcs(yp + (i + 1) * W4, o);
        TAP(o, w2, w3, w4, w5, w6, n0, n1); __stcs(yp + (i + 2) * W4, o);
        TAP(o, w3, w4, w5, w6, n0, n1, n2); __stcs(yp + (i + 3) * W4, o);

        // Second half-batch (g+16..g+19) — after w0..w3 freed (no spill).
        float4 m4 = __ldcs(xp + refl(g + 16) * W4);
        float4 m5 = __ldcs(xp + refl(g + 17) * W4);
        float4 m6 = __ldcs(xp + refl(g + 18) * W4);
        float4 m7 = __ldcs(xp + refl(g + 19) * W4);

        // Rows g+4..g+7.
        TAP(o, w4, w5, w6, n0, n1, n2, n3); __stcs(yp + (i + 4) * W4, o);
        TAP(o, w5, w6, n0, n1, n2, n3, n4); __stcs(yp + (i + 5) * W4, o);
        TAP(o, w6, n0, n1, n2, n3, n4, n5); __stcs(yp + (i + 6) * W4, o);
        TAP(o, n0, n1, n2, n3, n4, n5, n6); __stcs(yp + (i + 7) * W4, o);

        // Shift window by 8 rows.
        w0 = n1; w1 = n2; w2 = n3; w3 = n4; w4 = n5; w5 = n6; w6 = n7;
        n0 = m0; n1 = m1; n2 = m2; n3 = m3; n4 = m4; n5 = m5; n6 = m6; n7 = m7;
    }
#undef TAP
}

extern "C" void kernel_launch(void* const* d_in, const int* in_sizes, int n_in,
                              void* d_out, int out_size)
{
    const float4* x     = (const float4*)d_in[0];
    const float*  alpha = (const float*)d_in[1];
    float4*       y     = (float4*)d_out;

    const int C      = in_sizes[1] / 4;          // alpha is (C, 4)
    const int planes = in_sizes[0] / (HH * WW);  // N * C
    const int nunits = planes * SEGS;

    hartley_conv_kernel<<<nunits, 64>>>(x, alpha, y, nunits, C);
}